// round 16
// baseline (speedup 1.0000x reference)
#include <cuda_runtime.h>
#include <cuda_fp16.h>
#include <cstdint>

#define BB 4
#define TT 2048
#define FF 1024
#define HH 16
#define DH 64
#define SCALE 0.03125f            // 1024^-0.5
#define QSCALE (0.03125f * 1.44269504f)   // SCALE * log2(e): softmax in exp2 domain

// Scratch (device globals: allocation-free, harness-legal). fp16 operands.
__device__ __align__(1024) __half g_x [(size_t)BB * TT * FF];
__device__ __align__(1024) __half g_wq[(size_t)3 * FF * FF];   // w_qkv permuted [kq,hq,d][f]
__device__ __align__(1024) __half g_wo[(size_t)FF * FF];
__device__ __align__(1024) __half g_qkv[(size_t)3 * BB * HH * TT * DH]; // [k][b][h][t][d]
__device__ __align__(1024) __half g_ao[(size_t)BB * HH * TT * DH];      // [b][h][t][d]

__device__ __forceinline__ void mma16(float c[4], const uint32_t a[4],
                                      uint32_t b0, uint32_t b1) {
    asm volatile(
        "mma.sync.aligned.m16n8k16.row.col.f32.f16.f16.f32 "
        "{%0,%1,%2,%3},{%4,%5,%6,%7},{%8,%9},{%0,%1,%2,%3};"
        : "+f"(c[0]), "+f"(c[1]), "+f"(c[2]), "+f"(c[3])
        : "r"(a[0]), "r"(a[1]), "r"(a[2]), "r"(a[3]), "r"(b0), "r"(b1));
}
__device__ __forceinline__ void ldsm4(uint32_t r[4], uint32_t a) {
    asm volatile("ldmatrix.sync.aligned.m8n8.x4.shared.b16 {%0,%1,%2,%3}, [%4];"
                 : "=r"(r[0]), "=r"(r[1]), "=r"(r[2]), "=r"(r[3]) : "r"(a));
}
__device__ __forceinline__ void ldsm4t(uint32_t r[4], uint32_t a) {
    asm volatile("ldmatrix.sync.aligned.m8n8.x4.trans.shared.b16 {%0,%1,%2,%3}, [%4];"
                 : "=r"(r[0]), "=r"(r[1]), "=r"(r[2]), "=r"(r[3]) : "r"(a));
}
__device__ __forceinline__ void cpa16(uint32_t s, const void* g) {
    asm volatile("cp.async.cg.shared.global [%0], [%1], 16;" :: "r"(s), "l"(g));
}
__device__ __forceinline__ void cpa_commit() {
    asm volatile("cp.async.commit_group;");
}
template<int N> __device__ __forceinline__ void cpa_wait() {
    asm volatile("cp.async.wait_group %0;" :: "n"(N));
}
__device__ __forceinline__ uint32_t hexp2x2(uint32_t s) {
    uint32_t r; asm("ex2.approx.f16x2 %0, %1;" : "=r"(r) : "r"(s)); return r;
}

// ---------------------------------------------------------------------------
// Pre-pass: fp32 -> fp16; permute w_qkv rows (o = d*48 + kq*16 + hq).
// ---------------------------------------------------------------------------
#define XT4 ((size_t)BB * TT * FF / 4)
#define WQ4 ((size_t)3 * FF * FF / 4)
#define WO4 ((size_t)FF * FF / 4)

__global__ __launch_bounds__(256) void conv_kernel(const float* __restrict__ x,
                                                   const float* __restrict__ wq,
                                                   const float* __restrict__ wo) {
    size_t i = (size_t)blockIdx.x * 256 + threadIdx.x;
    const float4* src; __half* dst;
    if (i < XT4) {
        src = (const float4*)x + i; dst = g_x + i * 4;
    } else if (i < XT4 + WQ4) {
        size_t j = i - XT4;
        int n = (int)(j >> 8), c4 = (int)(j & 255);
        int kq = n >> 10, hq = (n >> 6) & 15, d = n & 63;
        src = (const float4*)(wq + (size_t)(d * 48 + kq * 16 + hq) * FF) + c4;
        dst = g_wq + (size_t)n * FF + c4 * 4;
    } else if (i < XT4 + WQ4 + WO4) {
        size_t j = i - XT4 - WQ4;
        src = (const float4*)wo + j; dst = g_wo + j * 4;
    } else return;
    float4 v = *src;
    *(__half2*)dst       = __floats2half2_rn(v.x, v.y);
    *(__half2*)(dst + 2) = __floats2half2_rn(v.z, v.w);
}

// ---------------------------------------------------------------------------
// fp16 GEMM (R13 config): CTA 128x128, 4 warps (2m x 2n), warp tile 64x64,
// k-tile 64, 2-stage cp.async double buffer, 2 CTAs/SM.
// Rows padded to 72 halves (conflict-free LDSM).
// MODE 0: A=g_x, B=g_wq  -> g_qkv fp16 (q rows pre-scaled by QSCALE)
// MODE 1: A=g_ao (k-tile kt == head kt), B=g_wo -> y fp32 + bias
// ---------------------------------------------------------------------------
#define RL 72
#define RB 144
#define GAST (128 * RB)             // one A or B stage: 18432 B
#define GEMM_SMEM (4 * GAST)        // 73728 B

template<int MODE>
__global__ __launch_bounds__(128, 2)
void gemm_w(const float* __restrict__ bias, float* __restrict__ out) {
    extern __shared__ __half smh[];
    const uint32_t sbase = (uint32_t)__cvta_generic_to_shared(smh);

    const int tid = threadIdx.x;
    const int lane = tid & 31, w = tid >> 5;
    const int g = lane >> 2, tig = lane & 3;
    const int wm = (w >> 1) * 64, wn = (w & 1) * 64;
    const int m0 = blockIdx.y * 128, n0 = blockIdx.x * 128;
    const int lrow = tid >> 3;              // 0..15
    const int kc = (tid & 7) * 8;

    const int arow_l = (lane & 7) + ((lane >> 3) & 1) * 8;
    const int acol_l = (lane >> 4) * 8;
    const int brow_l = (lane & 7) + (lane >> 4) * 8;
    const int bcol_l = ((lane >> 3) & 1) * 8;

    float acc[4][8][4];
    #pragma unroll
    for (int mt = 0; mt < 4; mt++)
        #pragma unroll
        for (int nt = 0; nt < 8; nt++)
            #pragma unroll
            for (int i = 0; i < 4; i++) acc[mt][nt][i] = 0.f;

    auto issue = [&](int stage, int kt) {
        const int k0 = kt * 64;
        #pragma unroll
        for (int r = 0; r < 8; r++) {
            int row = lrow + r * 16;
            const __half* src;
            if (MODE == 0) {
                src = g_x + (size_t)(m0 + row) * FF + k0 + kc;
            } else {
                int m = m0 + row; int b = m >> 11, t = m & 2047;
                src = g_ao + (((size_t)b * HH + kt) * TT + t) * DH + kc;
            }
            cpa16(sbase + stage * GAST + row * RB + kc * 2, src);
        }
        #pragma unroll
        for (int r = 0; r < 8; r++) {
            int row = lrow + r * 16;
            const __half* src = (MODE == 0 ? g_wq : g_wo) +
                                (size_t)(n0 + row) * FF + k0 + kc;
            cpa16(sbase + 2 * GAST + stage * GAST + row * RB + kc * 2, src);
        }
        cpa_commit();
    };

    issue(0, 0);
    const int NK = FF / 64;
    #pragma unroll 1
    for (int kt = 0; kt < NK; kt++) {
        cpa_wait<0>();
        __syncthreads();
        if (kt + 1 < NK) issue((kt + 1) & 1, kt + 1);

        const uint32_t aoff = sbase + (kt & 1) * GAST;
        const uint32_t boff = sbase + 2 * GAST + (kt & 1) * GAST;
        #pragma unroll
        for (int kk = 0; kk < 4; kk++) {
            uint32_t a[4][4], b[8][2];
            #pragma unroll
            for (int mt = 0; mt < 4; mt++)
                ldsm4(a[mt], aoff + (wm + mt * 16 + arow_l) * RB +
                              (kk * 16 + acol_l) * 2);
            #pragma unroll
            for (int ng = 0; ng < 4; ng++) {
                uint32_t t4[4];
                ldsm4(t4, boff + (wn + ng * 16 + brow_l) * RB +
                           (kk * 16 + bcol_l) * 2);
                b[2 * ng][0] = t4[0]; b[2 * ng][1] = t4[1];
                b[2 * ng + 1][0] = t4[2]; b[2 * ng + 1][1] = t4[3];
            }
            #pragma unroll
            for (int mt = 0; mt < 4; mt++)
                #pragma unroll
                for (int nt = 0; nt < 8; nt++)
                    mma16(acc[mt][nt], a[mt], b[nt][0], b[nt][1]);
        }
    }

    #pragma unroll
    for (int mt = 0; mt < 4; mt++)
        #pragma unroll
        for (int nt = 0; nt < 8; nt++) {
            int n = n0 + wn + nt * 8 + 2 * tig;
            #pragma unroll
            for (int half = 0; half < 2; half++) {
                int m = m0 + wm + mt * 16 + g + half * 8;
                float c0 = acc[mt][nt][half * 2 + 0];
                float c1 = acc[mt][nt][half * 2 + 1];
                if (MODE == 0) {
                    int b = m >> 11, t = m & 2047;
                    int kq = n >> 10, hq = (n >> 6) & 15, d = n & 63;
                    float sc = (kq == 0) ? QSCALE : 1.0f;
                    *(__half2*)&g_qkv[((((size_t)kq * BB + b) * HH + hq) * TT + t) * DH + d] =
                        __floats2half2_rn(c0 * sc, c1 * sc);
                } else {
                    float2 bv = *(const float2*)&bias[n];
                    *(float2*)&out[(size_t)m * FF + n] =
                        make_float2(c0 + bv.x, c1 + bv.y);
                }
            }
        }
}

// ---------------------------------------------------------------------------
// fp16 flash attention, register-resident P, no-max exp2 softmax.
// 4 warps x 32 q-rows; j-window 128 keys per cpa_wait/__syncthreads
// (two sequential 64-column compute passes reuse the sc/ph registers).
// grid=(T/128, B*H), 128 threads, 2 CTAs/SM. smem 72 KB.
// ---------------------------------------------------------------------------
#define AKST2 (128 * RB)            // 18432 B per K or V stage (128 rows)
#define ATTN_SMEM (4 * AKST2)       // 73728 B

__global__ __launch_bounds__(128, 2) void attn_h() {
    extern __shared__ __half smh[];
    const uint32_t sbase = (uint32_t)__cvta_generic_to_shared(smh);
    const uint32_t voffB = 2 * AKST2;

    const int tid = threadIdx.x, lane = tid & 31, w = tid >> 5;
    const int g = lane >> 2, tig = lane & 3;
    const int bh = blockIdx.y, i0 = blockIdx.x * 128;

    const __half* Qg = g_qkv + ((size_t)bh * TT + i0) * DH;
    const __half* Kg = g_qkv + (size_t)BB * HH * TT * DH + (size_t)bh * TT * DH;
    const __half* Vg = Kg + (size_t)BB * HH * TT * DH;

    const int arow_l = (lane & 7) + ((lane >> 3) & 1) * 8;   // A-pattern rows
    const int acol_l = (lane >> 4) * 8;
    const int brow_l = (lane & 7) + (lane >> 4) * 8;         // B-pattern rows
    const int bcol_l = ((lane >> 3) & 1) * 8;

    // Stage Q (128 rows, 18.4 KB) into the K stage space, preload frags.
    #pragma unroll
    for (int rep = 0; rep < 8; rep++) {
        int ii = rep * 128 + tid;
        int row = ii >> 3, c = (ii & 7) * 8;
        *(uint4*)&smh[row * RL + c] = *(const uint4*)(Qg + (size_t)row * DH + c);
    }
    __syncthreads();
    uint32_t qa[2][4][4];                       // [subtile][kk][frag]
    #pragma unroll
    for (int r = 0; r < 2; r++)
        #pragma unroll
        for (int kk = 0; kk < 4; kk++)
            ldsm4(qa[r][kk], sbase + (w * 32 + r * 16 + arow_l) * RB +
                              (kk * 16 + acol_l) * 2);
    __syncthreads();   // Q staging done before K loads overwrite

    // Load a 128-row K window + 128-row V window into stage.
    auto issue = [&](int stage, int j0) {
        #pragma unroll
        for (int r = 0; r < 8; r++) {
            int ii = r * 128 + tid;
            int row = ii >> 3, c = (ii & 7) * 8;
            cpa16(sbase + stage * AKST2 + row * RB + c * 2,
                  Kg + (size_t)(j0 + row) * DH + c);
            cpa16(sbase + voffB + stage * AKST2 + row * RB + c * 2,
                  Vg + (size_t)(j0 + row) * DH + c);
        }
        cpa_commit();
    };

    float oc[2][8][4];
    float li[2][2] = {{0.f, 0.f}, {0.f, 0.f}};
    #pragma unroll
    for (int r = 0; r < 2; r++)
        #pragma unroll
        for (int nt = 0; nt < 8; nt++)
            #pragma unroll
            for (int i = 0; i < 4; i++) oc[r][nt][i] = 0.f;

    issue(0, 0);
    const int NJ = TT / 128;
    #pragma unroll 1
    for (int jt = 0; jt < NJ; jt++) {
        cpa_wait<0>();
        __syncthreads();
        if (jt + 1 < NJ) issue((jt + 1) & 1, (jt + 1) * 128);

        const uint32_t kb0 = sbase + (jt & 1) * AKST2;
        const uint32_t vb0 = sbase + voffB + (jt & 1) * AKST2;

        #pragma unroll
        for (int pass = 0; pass < 2; pass++) {
            const uint32_t kbp = kb0 + pass * 64 * RB;
            const uint32_t vbp = vb0 + pass * 64 * RB;

            // S = Q K^T (scores already in log2 domain via QSCALE)
            float sc_[2][8][4];
            #pragma unroll
            for (int r = 0; r < 2; r++)
                #pragma unroll
                for (int nt = 0; nt < 8; nt++)
                    #pragma unroll
                    for (int i = 0; i < 4; i++) sc_[r][nt][i] = 0.f;
            #pragma unroll
            for (int kk = 0; kk < 4; kk++) {
                uint32_t b[8][2];
                #pragma unroll
                for (int ng = 0; ng < 4; ng++) {
                    uint32_t t4[4];
                    ldsm4(t4, kbp + (ng * 16 + brow_l) * RB + (kk * 16 + bcol_l) * 2);
                    b[2 * ng][0] = t4[0]; b[2 * ng][1] = t4[1];
                    b[2 * ng + 1][0] = t4[2]; b[2 * ng + 1][1] = t4[3];
                }
                #pragma unroll
                for (int nt = 0; nt < 8; nt++) {
                    mma16(sc_[0][nt], qa[0][kk], b[nt][0], b[nt][1]);
                    mma16(sc_[1][nt], qa[1][kk], b[nt][0], b[nt][1]);
                }
            }

            // p = exp2(s); P stays in registers (exact PV A-fragments).
            uint32_t ph[2][8][2];
            #pragma unroll
            for (int r = 0; r < 2; r++) {
                __half2 va0 = __float2half2_rn(0.f), va1 = __float2half2_rn(0.f);
                #pragma unroll
                for (int nt = 0; nt < 8; nt++) {
                    __half2 h0 = __floats2half2_rn(sc_[r][nt][0], sc_[r][nt][1]);
                    __half2 h1 = __floats2half2_rn(sc_[r][nt][2], sc_[r][nt][3]);
                    uint32_t p0 = hexp2x2(*(uint32_t*)&h0);
                    uint32_t p1 = hexp2x2(*(uint32_t*)&h1);
                    ph[r][nt][0] = p0; ph[r][nt][1] = p1;
                    va0 = __hadd2(va0, *(__half2*)&p0);
                    va1 = __hadd2(va1, *(__half2*)&p1);
                }
                float2 f0 = __half22float2(va0);
                float2 f1 = __half22float2(va1);
                li[r][0] += f0.x + f0.y;
                li[r][1] += f1.x + f1.y;
            }

            // O += P V (V B-frags via ldmatrix.trans, shared by both subtiles)
            #pragma unroll
            for (int kk = 0; kk < 4; kk++) {
                uint32_t pa0[4] = {ph[0][2 * kk][0], ph[0][2 * kk][1],
                                   ph[0][2 * kk + 1][0], ph[0][2 * kk + 1][1]};
                uint32_t pa1[4] = {ph[1][2 * kk][0], ph[1][2 * kk][1],
                                   ph[1][2 * kk + 1][0], ph[1][2 * kk + 1][1]};
                uint32_t vb[8][2];
                #pragma unroll
                for (int dg = 0; dg < 4; dg++) {
                    uint32_t t4[4];
                    ldsm4t(t4, vbp + (kk * 16 + arow_l) * RB + (dg * 16 + acol_l) * 2);
                    vb[2 * dg][0] = t4[0]; vb[2 * dg][1] = t4[1];
                    vb[2 * dg + 1][0] = t4[2]; vb[2 * dg + 1][1] = t4[3];
                }
                #pragma unroll
                for (int nt = 0; nt < 8; nt++) {
                    mma16(oc[0][nt], pa0, vb[nt][0], vb[nt][1]);
                    mma16(oc[1][nt], pa1, vb[nt][0], vb[nt][1]);
                }
            }
        }
    }

    // Deferred li reduction across the 4 tig lanes; normalize and store.
    #pragma unroll
    for (int r = 0; r < 2; r++) {
        li[r][0] += __shfl_xor_sync(0xffffffffu, li[r][0], 1);
        li[r][0] += __shfl_xor_sync(0xffffffffu, li[r][0], 2);
        li[r][1] += __shfl_xor_sync(0xffffffffu, li[r][1], 1);
        li[r][1] += __shfl_xor_sync(0xffffffffu, li[r][1], 2);
        float inv0 = 1.f / li[r][0], inv1 = 1.f / li[r][1];
        int r0 = i0 + w * 32 + r * 16 + g, r1 = r0 + 8;
        #pragma unroll
        for (int nt = 0; nt < 8; nt++) {
            int d = nt * 8 + 2 * tig;
            *(__half2*)&g_ao[((size_t)bh * TT + r0) * DH + d] =
                __floats2half2_rn(oc[r][nt][0] * inv0, oc[r][nt][1] * inv0);
            *(__half2*)&g_ao[((size_t)bh * TT + r1) * DH + d] =
                __floats2half2_rn(oc[r][nt][2] * inv1, oc[r][nt][3] * inv1);
        }
    }
}

// ---------------------------------------------------------------------------
extern "C" void kernel_launch(void* const* d_in, const int* in_sizes, int n_in,
                              void* d_out, int out_size) {
    const float* x    = (const float*)d_in[0];
    const float* wqkv = (const float*)d_in[1];
    const float* wout = (const float*)d_in[2];
    const float* bout = (const float*)d_in[3];
    float* y = (float*)d_out;

    cudaFuncSetAttribute((const void*)gemm_w<0>,
                         cudaFuncAttributeMaxDynamicSharedMemorySize, GEMM_SMEM);
    cudaFuncSetAttribute((const void*)gemm_w<1>,
                         cudaFuncAttributeMaxDynamicSharedMemorySize, GEMM_SMEM);
    cudaFuncSetAttribute((const void*)attn_h,
                         cudaFuncAttributeMaxDynamicSharedMemorySize, ATTN_SMEM);

    size_t total4 = XT4 + WQ4 + WO4;
    conv_kernel<<<(unsigned)((total4 + 255) / 256), 256>>>(x, wqkv, wout);
    gemm_w<0><<<dim3(24, 64), 128, GEMM_SMEM>>>(nullptr, nullptr);
    attn_h<<<dim3(TT / 128, BB * HH), 128, ATTN_SMEM>>>();
    gemm_w<1><<<dim3(8, 64), 128, GEMM_SMEM>>>(bout, y);
}

// round 17
// speedup vs baseline: 1.5580x; 1.5580x over previous
#include <cuda_runtime.h>
#include <cuda_fp16.h>
#include <cstdint>

#define BB 4
#define TT 2048
#define FF 1024
#define HH 16
#define DH 64
#define SCALE 0.03125f            // 1024^-0.5
#define QSCALE (0.03125f * 1.44269504f)   // SCALE * log2(e): softmax in exp2 domain

// Scratch (device globals: allocation-free, harness-legal). fp16 operands.
__device__ __align__(1024) __half g_x [(size_t)BB * TT * FF];
__device__ __align__(1024) __half g_wq[(size_t)3 * FF * FF];   // w_qkv permuted [kq,hq,d][f]
__device__ __align__(1024) __half g_wo[(size_t)FF * FF];
__device__ __align__(1024) __half g_qkv[(size_t)3 * BB * HH * TT * DH]; // [k][b][h][t][d]
__device__ __align__(1024) __half g_ao[(size_t)BB * HH * TT * DH];      // [b][h][t][d]

__device__ __forceinline__ void mma16(float c[4], const uint32_t a[4],
                                      uint32_t b0, uint32_t b1) {
    asm volatile(
        "mma.sync.aligned.m16n8k16.row.col.f32.f16.f16.f32 "
        "{%0,%1,%2,%3},{%4,%5,%6,%7},{%8,%9},{%0,%1,%2,%3};"
        : "+f"(c[0]), "+f"(c[1]), "+f"(c[2]), "+f"(c[3])
        : "r"(a[0]), "r"(a[1]), "r"(a[2]), "r"(a[3]), "r"(b0), "r"(b1));
}
__device__ __forceinline__ void ldsm4(uint32_t r[4], uint32_t a) {
    asm volatile("ldmatrix.sync.aligned.m8n8.x4.shared.b16 {%0,%1,%2,%3}, [%4];"
                 : "=r"(r[0]), "=r"(r[1]), "=r"(r[2]), "=r"(r[3]) : "r"(a));
}
__device__ __forceinline__ void ldsm4t(uint32_t r[4], uint32_t a) {
    asm volatile("ldmatrix.sync.aligned.m8n8.x4.trans.shared.b16 {%0,%1,%2,%3}, [%4];"
                 : "=r"(r[0]), "=r"(r[1]), "=r"(r[2]), "=r"(r[3]) : "r"(a));
}
__device__ __forceinline__ void cpa16(uint32_t s, const void* g) {
    asm volatile("cp.async.cg.shared.global [%0], [%1], 16;" :: "r"(s), "l"(g));
}
__device__ __forceinline__ void cpa_commit() {
    asm volatile("cp.async.commit_group;");
}
template<int N> __device__ __forceinline__ void cpa_wait() {
    asm volatile("cp.async.wait_group %0;" :: "n"(N));
}
__device__ __forceinline__ uint32_t hexp2x2(uint32_t s) {
    uint32_t r; asm("ex2.approx.f16x2 %0, %1;" : "=r"(r) : "r"(s)); return r;
}

// ---------------------------------------------------------------------------
// Pre-pass: fp32 -> fp16; permute w_qkv rows (o = d*48 + kq*16 + hq).
// ---------------------------------------------------------------------------
#define XT4 ((size_t)BB * TT * FF / 4)
#define WQ4 ((size_t)3 * FF * FF / 4)
#define WO4 ((size_t)FF * FF / 4)

__global__ __launch_bounds__(256) void conv_kernel(const float* __restrict__ x,
                                                   const float* __restrict__ wq,
                                                   const float* __restrict__ wo) {
    size_t i = (size_t)blockIdx.x * 256 + threadIdx.x;
    const float4* src; __half* dst;
    if (i < XT4) {
        src = (const float4*)x + i; dst = g_x + i * 4;
    } else if (i < XT4 + WQ4) {
        size_t j = i - XT4;
        int n = (int)(j >> 8), c4 = (int)(j & 255);
        int kq = n >> 10, hq = (n >> 6) & 15, d = n & 63;
        src = (const float4*)(wq + (size_t)(d * 48 + kq * 16 + hq) * FF) + c4;
        dst = g_wq + (size_t)n * FF + c4 * 4;
    } else if (i < XT4 + WQ4 + WO4) {
        size_t j = i - XT4 - WQ4;
        src = (const float4*)wo + j; dst = g_wo + j * 4;
    } else return;
    float4 v = *src;
    *(__half2*)dst       = __floats2half2_rn(v.x, v.y);
    *(__half2*)(dst + 2) = __floats2half2_rn(v.z, v.w);
}

// ---------------------------------------------------------------------------
// fp16 GEMM (R13 config): CTA 128x128, 4 warps (2m x 2n), warp tile 64x64,
// k-tile 64, 2-stage cp.async double buffer, 2 CTAs/SM.
// Rows padded to 72 halves (conflict-free LDSM).
// MODE 0: A=g_x, B=g_wq  -> g_qkv fp16 (q rows pre-scaled by QSCALE)
// MODE 1: A=g_ao (k-tile kt == head kt), B=g_wo -> y fp32 + bias
// ---------------------------------------------------------------------------
#define RL 72
#define RB 144
#define GAST (128 * RB)             // one A or B stage: 18432 B
#define GEMM_SMEM (4 * GAST)        // 73728 B

template<int MODE>
__global__ __launch_bounds__(128, 2)
void gemm_w(const float* __restrict__ bias, float* __restrict__ out) {
    extern __shared__ __half smh[];
    const uint32_t sbase = (uint32_t)__cvta_generic_to_shared(smh);

    const int tid = threadIdx.x;
    const int lane = tid & 31, w = tid >> 5;
    const int g = lane >> 2, tig = lane & 3;
    const int wm = (w >> 1) * 64, wn = (w & 1) * 64;
    const int m0 = blockIdx.y * 128, n0 = blockIdx.x * 128;
    const int lrow = tid >> 3;              // 0..15
    const int kc = (tid & 7) * 8;

    const int arow_l = (lane & 7) + ((lane >> 3) & 1) * 8;
    const int acol_l = (lane >> 4) * 8;
    const int brow_l = (lane & 7) + (lane >> 4) * 8;
    const int bcol_l = ((lane >> 3) & 1) * 8;

    float acc[4][8][4];
    #pragma unroll
    for (int mt = 0; mt < 4; mt++)
        #pragma unroll
        for (int nt = 0; nt < 8; nt++)
            #pragma unroll
            for (int i = 0; i < 4; i++) acc[mt][nt][i] = 0.f;

    auto issue = [&](int stage, int kt) {
        const int k0 = kt * 64;
        #pragma unroll
        for (int r = 0; r < 8; r++) {
            int row = lrow + r * 16;
            const __half* src;
            if (MODE == 0) {
                src = g_x + (size_t)(m0 + row) * FF + k0 + kc;
            } else {
                int m = m0 + row; int b = m >> 11, t = m & 2047;
                src = g_ao + (((size_t)b * HH + kt) * TT + t) * DH + kc;
            }
            cpa16(sbase + stage * GAST + row * RB + kc * 2, src);
        }
        #pragma unroll
        for (int r = 0; r < 8; r++) {
            int row = lrow + r * 16;
            const __half* src = (MODE == 0 ? g_wq : g_wo) +
                                (size_t)(n0 + row) * FF + k0 + kc;
            cpa16(sbase + 2 * GAST + stage * GAST + row * RB + kc * 2, src);
        }
        cpa_commit();
    };

    issue(0, 0);
    const int NK = FF / 64;
    #pragma unroll 1
    for (int kt = 0; kt < NK; kt++) {
        cpa_wait<0>();
        __syncthreads();
        if (kt + 1 < NK) issue((kt + 1) & 1, kt + 1);

        const uint32_t aoff = sbase + (kt & 1) * GAST;
        const uint32_t boff = sbase + 2 * GAST + (kt & 1) * GAST;
        #pragma unroll
        for (int kk = 0; kk < 4; kk++) {
            uint32_t a[4][4], b[8][2];
            #pragma unroll
            for (int mt = 0; mt < 4; mt++)
                ldsm4(a[mt], aoff + (wm + mt * 16 + arow_l) * RB +
                              (kk * 16 + acol_l) * 2);
            #pragma unroll
            for (int ng = 0; ng < 4; ng++) {
                uint32_t t4[4];
                ldsm4(t4, boff + (wn + ng * 16 + brow_l) * RB +
                           (kk * 16 + bcol_l) * 2);
                b[2 * ng][0] = t4[0]; b[2 * ng][1] = t4[1];
                b[2 * ng + 1][0] = t4[2]; b[2 * ng + 1][1] = t4[3];
            }
            #pragma unroll
            for (int mt = 0; mt < 4; mt++)
                #pragma unroll
                for (int nt = 0; nt < 8; nt++)
                    mma16(acc[mt][nt], a[mt], b[nt][0], b[nt][1]);
        }
    }

    #pragma unroll
    for (int mt = 0; mt < 4; mt++)
        #pragma unroll
        for (int nt = 0; nt < 8; nt++) {
            int n = n0 + wn + nt * 8 + 2 * tig;
            #pragma unroll
            for (int half = 0; half < 2; half++) {
                int m = m0 + wm + mt * 16 + g + half * 8;
                float c0 = acc[mt][nt][half * 2 + 0];
                float c1 = acc[mt][nt][half * 2 + 1];
                if (MODE == 0) {
                    int b = m >> 11, t = m & 2047;
                    int kq = n >> 10, hq = (n >> 6) & 15, d = n & 63;
                    float sc = (kq == 0) ? QSCALE : 1.0f;
                    *(__half2*)&g_qkv[((((size_t)kq * BB + b) * HH + hq) * TT + t) * DH + d] =
                        __floats2half2_rn(c0 * sc, c1 * sc);
                } else {
                    float2 bv = *(const float2*)&bias[n];
                    *(float2*)&out[(size_t)m * FF + n] =
                        make_float2(c0 + bv.x, c1 + bv.y);
                }
            }
        }
}

// ---------------------------------------------------------------------------
// fp16 flash attention (R13 config), register-resident P, no-max exp2
// softmax. 4 warps x 32 q-rows (two 16-row subtiles share ALL K/V B-frags:
// 0.25 LDSM/mma). grid=(T/128, B*H), 128 threads, 2 CTAs/SM.
// li accumulated per-j-tile in f16x2 (HADD2), promoted to f32 per tile.
// ---------------------------------------------------------------------------
#define AKST (64 * RB)              // 9216 B per K or V stage
#define ATTN_SMEM (4 * AKST)        // 36864 B

__global__ __launch_bounds__(128, 2) void attn_h() {
    extern __shared__ __half smh[];
    const uint32_t sbase = (uint32_t)__cvta_generic_to_shared(smh);
    const uint32_t koffB = 0, voffB = 2 * AKST;

    const int tid = threadIdx.x, lane = tid & 31, w = tid >> 5;
    const int g = lane >> 2, tig = lane & 3;
    const int bh = blockIdx.y, i0 = blockIdx.x * 128;

    const __half* Qg = g_qkv + ((size_t)bh * TT + i0) * DH;
    const __half* Kg = g_qkv + (size_t)BB * HH * TT * DH + (size_t)bh * TT * DH;
    const __half* Vg = Kg + (size_t)BB * HH * TT * DH;

    const int arow_l = (lane & 7) + ((lane >> 3) & 1) * 8;   // A-pattern rows
    const int acol_l = (lane >> 4) * 8;
    const int brow_l = (lane & 7) + (lane >> 4) * 8;         // B-pattern rows
    const int bcol_l = ((lane >> 3) & 1) * 8;

    // Stage Q (128 rows) through the K+V double-buffer space, preload frags.
    #pragma unroll
    for (int rep = 0; rep < 8; rep++) {
        int ii = rep * 128 + tid;
        int row = ii >> 3, c = (ii & 7) * 8;
        *(uint4*)&smh[row * RL + c] = *(const uint4*)(Qg + (size_t)row * DH + c);
    }
    __syncthreads();
    uint32_t qa[2][4][4];                       // [subtile][kk][frag]
    #pragma unroll
    for (int r = 0; r < 2; r++)
        #pragma unroll
        for (int kk = 0; kk < 4; kk++)
            ldsm4(qa[r][kk], sbase + (w * 32 + r * 16 + arow_l) * RB +
                              (kk * 16 + acol_l) * 2);
    __syncthreads();   // Q staging done before K loads overwrite

    auto issue = [&](int stage, int j0) {
        #pragma unroll
        for (int r = 0; r < 4; r++) {
            int ii = r * 128 + tid;
            int row = ii >> 3, c = (ii & 7) * 8;
            cpa16(sbase + koffB + stage * AKST + row * RB + c * 2,
                  Kg + (size_t)(j0 + row) * DH + c);
            cpa16(sbase + voffB + stage * AKST + row * RB + c * 2,
                  Vg + (size_t)(j0 + row) * DH + c);
        }
        cpa_commit();
    };

    float oc[2][8][4];
    float li[2][2] = {{0.f, 0.f}, {0.f, 0.f}};
    #pragma unroll
    for (int r = 0; r < 2; r++)
        #pragma unroll
        for (int nt = 0; nt < 8; nt++)
            #pragma unroll
            for (int i = 0; i < 4; i++) oc[r][nt][i] = 0.f;

    issue(0, 0);
    const int NJ = TT / 64;
    #pragma unroll 1
    for (int jt = 0; jt < NJ; jt++) {
        cpa_wait<0>();
        __syncthreads();
        if (jt + 1 < NJ) issue((jt + 1) & 1, (jt + 1) * 64);

        const uint32_t kb0 = sbase + koffB + (jt & 1) * AKST;
        const uint32_t vb0 = sbase + voffB + (jt & 1) * AKST;

        // S = Q K^T (scores already in log2 domain via QSCALE)
        float sc_[2][8][4];
        #pragma unroll
        for (int r = 0; r < 2; r++)
            #pragma unroll
            for (int nt = 0; nt < 8; nt++)
                #pragma unroll
                for (int i = 0; i < 4; i++) sc_[r][nt][i] = 0.f;
        #pragma unroll
        for (int kk = 0; kk < 4; kk++) {
            uint32_t b[8][2];
            #pragma unroll
            for (int ng = 0; ng < 4; ng++) {
                uint32_t t4[4];
                ldsm4(t4, kb0 + (ng * 16 + brow_l) * RB + (kk * 16 + bcol_l) * 2);
                b[2 * ng][0] = t4[0]; b[2 * ng][1] = t4[1];
                b[2 * ng + 1][0] = t4[2]; b[2 * ng + 1][1] = t4[3];
            }
            #pragma unroll
            for (int nt = 0; nt < 8; nt++) {
                mma16(sc_[0][nt], qa[0][kk], b[nt][0], b[nt][1]);
                mma16(sc_[1][nt], qa[1][kk], b[nt][0], b[nt][1]);
            }
        }

        // p = exp2(s); P stays in registers (exact PV A-fragments).
        // li chunk accumulated in f16x2 (HADD2), promoted to f32 per j-tile.
        uint32_t ph[2][8][2];
        #pragma unroll
        for (int r = 0; r < 2; r++) {
            __half2 va0 = __float2half2_rn(0.f), va1 = __float2half2_rn(0.f);
            #pragma unroll
            for (int nt = 0; nt < 8; nt++) {
                __half2 h0 = __floats2half2_rn(sc_[r][nt][0], sc_[r][nt][1]);
                __half2 h1 = __floats2half2_rn(sc_[r][nt][2], sc_[r][nt][3]);
                uint32_t p0 = hexp2x2(*(uint32_t*)&h0);
                uint32_t p1 = hexp2x2(*(uint32_t*)&h1);
                ph[r][nt][0] = p0; ph[r][nt][1] = p1;
                va0 = __hadd2(va0, *(__half2*)&p0);
                va1 = __hadd2(va1, *(__half2*)&p1);
            }
            float2 f0 = __half22float2(va0);
            float2 f1 = __half22float2(va1);
            li[r][0] += f0.x + f0.y;
            li[r][1] += f1.x + f1.y;
        }

        // O += P V (V B-frags via ldmatrix.trans, shared by both subtiles)
        #pragma unroll
        for (int kk = 0; kk < 4; kk++) {
            uint32_t pa0[4] = {ph[0][2 * kk][0], ph[0][2 * kk][1],
                               ph[0][2 * kk + 1][0], ph[0][2 * kk + 1][1]};
            uint32_t pa1[4] = {ph[1][2 * kk][0], ph[1][2 * kk][1],
                               ph[1][2 * kk + 1][0], ph[1][2 * kk + 1][1]};
            uint32_t vb[8][2];
            #pragma unroll
            for (int dg = 0; dg < 4; dg++) {
                uint32_t t4[4];
                ldsm4t(t4, vb0 + (kk * 16 + arow_l) * RB + (dg * 16 + acol_l) * 2);
                vb[2 * dg][0] = t4[0]; vb[2 * dg][1] = t4[1];
                vb[2 * dg + 1][0] = t4[2]; vb[2 * dg + 1][1] = t4[3];
            }
            #pragma unroll
            for (int nt = 0; nt < 8; nt++) {
                mma16(oc[0][nt], pa0, vb[nt][0], vb[nt][1]);
                mma16(oc[1][nt], pa1, vb[nt][0], vb[nt][1]);
            }
        }
    }

    // Deferred li reduction across the 4 tig lanes; normalize and store.
    #pragma unroll
    for (int r = 0; r < 2; r++) {
        li[r][0] += __shfl_xor_sync(0xffffffffu, li[r][0], 1);
        li[r][0] += __shfl_xor_sync(0xffffffffu, li[r][0], 2);
        li[r][1] += __shfl_xor_sync(0xffffffffu, li[r][1], 1);
        li[r][1] += __shfl_xor_sync(0xffffffffu, li[r][1], 2);
        float inv0 = 1.f / li[r][0], inv1 = 1.f / li[r][1];
        int r0 = i0 + w * 32 + r * 16 + g, r1 = r0 + 8;
        #pragma unroll
        for (int nt = 0; nt < 8; nt++) {
            int d = nt * 8 + 2 * tig;
            *(__half2*)&g_ao[((size_t)bh * TT + r0) * DH + d] =
                __floats2half2_rn(oc[r][nt][0] * inv0, oc[r][nt][1] * inv0);
            *(__half2*)&g_ao[((size_t)bh * TT + r1) * DH + d] =
                __floats2half2_rn(oc[r][nt][2] * inv1, oc[r][nt][3] * inv1);
        }
    }
}

// ---------------------------------------------------------------------------
extern "C" void kernel_launch(void* const* d_in, const int* in_sizes, int n_in,
                              void* d_out, int out_size) {
    const float* x    = (const float*)d_in[0];
    const float* wqkv = (const float*)d_in[1];
    const float* wout = (const float*)d_in[2];
    const float* bout = (const float*)d_in[3];
    float* y = (float*)d_out;

    cudaFuncSetAttribute((const void*)gemm_w<0>,
                         cudaFuncAttributeMaxDynamicSharedMemorySize, GEMM_SMEM);
    cudaFuncSetAttribute((const void*)gemm_w<1>,
                         cudaFuncAttributeMaxDynamicSharedMemorySize, GEMM_SMEM);
    cudaFuncSetAttribute((const void*)attn_h,
                         cudaFuncAttributeMaxDynamicSharedMemorySize, ATTN_SMEM);

    size_t total4 = XT4 + WQ4 + WO4;
    conv_kernel<<<(unsigned)((total4 + 255) / 256), 256>>>(x, wqkv, wout);
    gemm_w<0><<<dim3(24, 64), 128, GEMM_SMEM>>>(nullptr, nullptr);
    attn_h<<<dim3(TT / 128, BB * HH), 128, ATTN_SMEM>>>();
    gemm_w<1><<<dim3(8, 64), 128, GEMM_SMEM>>>(bout, y);
}